// round 8
// baseline (speedup 1.0000x reference)
#include <cuda_runtime.h>
#include <cuda_fp16.h>
#include <cstdint>

#define H 128

// Scratch: c[g] = s[g] @ W1[128:256] + b1  (fp32).
__device__ float g_c[4096 * 128];

// ============================================================================
// Base-target PTX helpers
// ============================================================================
__device__ __forceinline__ uint32_t pack_f16x2(float lo, float hi) {
    uint32_t u;
    asm("cvt.rn.f16x2.f32 %0, %1, %2;" : "=r"(u) : "f"(hi), "f"(lo));
    return u;
}
__device__ __forceinline__ uint32_t smem_u32_of(const void* p) {
    uint32_t a;
    asm("{ .reg .u64 t; cvta.to.shared.u64 t, %1; cvt.u32.u64 %0, t; }"
        : "=r"(a) : "l"(p));
    return a;
}
__device__ __forceinline__ void mma16(float* d, const uint32_t* a,
                                      uint32_t b0, uint32_t b1) {
    asm volatile(
        "mma.sync.aligned.m16n8k16.row.col.f32.f16.f16.f32 "
        "{%0,%1,%2,%3},{%4,%5,%6,%7},{%8,%9},{%0,%1,%2,%3};"
        : "+f"(d[0]), "+f"(d[1]), "+f"(d[2]), "+f"(d[3])
        : "r"(a[0]), "r"(a[1]), "r"(a[2]), "r"(a[3]), "r"(b0), "r"(b1));
}
__device__ __forceinline__ void ldsm4(uint32_t& r0, uint32_t& r1,
                                      uint32_t& r2, uint32_t& r3, uint32_t addr) {
    asm volatile("ldmatrix.sync.aligned.m8n8.x4.shared.b16 {%0,%1,%2,%3}, [%4];"
                 : "=r"(r0), "=r"(r1), "=r"(r2), "=r"(r3) : "r"(addr));
}

// ============================================================================
// Fused segment-sum + set MLP + c precompute (one kernel, no atomics).
// Block = 8 graphs, 128 threads (thread j = column j). seg is SORTED, so the
// block's node range comes from 9 binary searches; per-graph sums are direct.
// ============================================================================
__global__ void seg_mlp_c_kernel(const float* __restrict__ node,
                                 const int* __restrict__ seg,
                                 const float* __restrict__ uset,
                                 const float* __restrict__ Ws1,
                                 const float* __restrict__ bs1,
                                 const float* __restrict__ Ws2,
                                 const float* __restrict__ bs2,
                                 const float* __restrict__ W1g,
                                 const float* __restrict__ b1g,
                                 float* __restrict__ s_out,
                                 int N) {
    __shared__ int bnds[9];
    __shared__ float x[8][256];
    __shared__ float h1[8][128];
    __shared__ float sres[8][128];
    const int j = threadIdx.x;
    const int g0 = blockIdx.x * 8;

    if (j <= 8) {
        int lo = 0, hi = N;
        const int key = g0 + j;
        while (lo < hi) {
            int m = (lo + hi) >> 1;
            if (seg[m] < key) lo = m + 1; else hi = m;
        }
        bnds[j] = lo;
    }
    __syncthreads();

    #pragma unroll
    for (int r = 0; r < 8; ++r) {
        float a = 0.0f;
        const int s = bnds[r], e = bnds[r + 1];
        int i = s;
        for (; i + 4 <= e; i += 4) {
            a += node[(size_t)(i + 0) * H + j];
            a += node[(size_t)(i + 1) * H + j];
            a += node[(size_t)(i + 2) * H + j];
            a += node[(size_t)(i + 3) * H + j];
        }
        for (; i < e; ++i) a += node[(size_t)i * H + j];
        x[r][j] = a;
        x[r][128 + j] = uset[(size_t)(g0 + r) * H + j];
    }
    __syncthreads();

    float acc[8];
    float b1 = bs1[j];
    #pragma unroll
    for (int r = 0; r < 8; ++r) acc[r] = b1;
    for (int k = 0; k < 256; ++k) {
        float w = Ws1[k * H + j];
        #pragma unroll
        for (int r = 0; r < 8; ++r) acc[r] += x[r][k] * w;
    }
    #pragma unroll
    for (int r = 0; r < 8; ++r) h1[r][j] = fmaxf(acc[r], 0.0f);
    __syncthreads();
    float b2 = bs2[j];
    #pragma unroll
    for (int r = 0; r < 8; ++r) acc[r] = b2;
    for (int k = 0; k < 128; ++k) {
        float w = Ws2[k * H + j];
        #pragma unroll
        for (int r = 0; r < 8; ++r) acc[r] += h1[r][k] * w;
    }
    #pragma unroll
    for (int r = 0; r < 8; ++r) {
        float v = fmaxf(acc[r], 0.0f);
        sres[r][j] = v;
        s_out[(size_t)(g0 + r) * H + j] = v;
    }
    __syncthreads();
    float bb = b1g[j];
    #pragma unroll
    for (int r = 0; r < 8; ++r) acc[r] = bb;
    for (int k = 0; k < 128; ++k) {
        float w = W1g[(size_t)(128 + k) * H + j];
        #pragma unroll
        for (int r = 0; r < 8; ++r) acc[r] += sres[r][k] * w;
    }
    #pragma unroll
    for (int r = 0; r < 8; ++r) g_c[(size_t)(g0 + r) * H + j] = acc[r];
}

// ============================================================================
// Fused node MLP, all-fp16 operands, fp32 accumulate.
//   layer1: acc = c[seg] (preloaded into accumulators) + X @ W1a ; relu -> h1
//   layer2: out = h1 @ W2 + b2 ; relu -> STG
// All smem tiles fp16, 256B/row, swizzle: o = row*256 + (((k>>3)^(row&7))<<4)
//                                             + (k&7)*2.
// X single 32KB buffer (K=128); refilled via LDG->cvt->STS during layer2.
// 2 barriers per tile.
// ============================================================================
#define W1_OFF   0        // 32768 (fp16)
#define W2_OFF   32768    // 32768 (fp16)
#define X_OFF    65536    // 32768 (fp16)
#define H1_OFF   98304    // 32768 (fp16)
#define B2S_OFF  131072   // 512
#define SEG_OFF  131584   // 512
#define F_SMEM   132096

__global__ void __launch_bounds__(512, 1)
fused_node_mlp(const float* __restrict__ node,
               const int* __restrict__ seg,
               const float* __restrict__ W1g,
               const float* __restrict__ W2g,
               const float* __restrict__ b2g,
               float* __restrict__ n_out,
               int numTiles) {
    extern __shared__ __align__(16) char smem[];
    const uint32_t sb = smem_u32_of(smem);
    float* b2s = (float*)(smem + B2S_OFF);
    int* segs = (int*)(smem + SEG_OFF);

    const int tid = threadIdx.x, lane = tid & 31, wid = tid >> 5;
    const int wr = wid & 3, wc = wid >> 2;
    const int gr = lane >> 2, tg = lane & 3;

    // X-fill mapping: thread -> row = tid&127, kb base = (tid>>7)*4 (+i, i<4)
    const int xrow = tid & 127;
    const int xkb0 = (tid >> 7) * 4;

    // one-time: W1a fp16, W2 fp16, bias
    for (int idx = tid; idx < 128 * 128; idx += 512) {
        int n = idx >> 7, k = idx & 127;
        uint32_t o = (uint32_t)n * 256u + ((((uint32_t)k >> 3) ^ (n & 7)) << 4)
                   + ((uint32_t)k & 7) * 2u;
        *(__half*)(smem + W1_OFF + o) = __float2half_rn(W1g[(size_t)k * H + n]);
        *(__half*)(smem + W2_OFF + o) = __float2half_rn(W2g[(size_t)k * H + n]);
    }
    if (tid < 128) b2s[tid] = b2g[tid];

    // ldsm lane constants
    const int subA = lane & 7;
    const int arow0 = wr * 32 + ((lane >> 3) & 1) * 8 + subA;  // + mt*16
    const int hA = lane >> 4;
    const int subB = lane & 7;
    const int brow0 = wc * 32 + ((lane >> 4) & 1) * 8 + subB;  // + p*16
    const int hB = (lane >> 3) & 1;

    // prologue: fill Xbuf for first tile
    if (blockIdx.x < numTiles) {
        const int base = blockIdx.x * 128;
        #pragma unroll
        for (int i = 0; i < 4; ++i) {
            const int kb = xkb0 + i;
            const float* src = &node[(size_t)(base + xrow) * H + kb * 8];
            float4 va = *(const float4*)src;
            float4 vb = *(const float4*)(src + 4);
            uint4 v;
            v.x = pack_f16x2(va.x, va.y); v.y = pack_f16x2(va.z, va.w);
            v.z = pack_f16x2(vb.x, vb.y); v.w = pack_f16x2(vb.z, vb.w);
            uint32_t o = (uint32_t)xrow * 256u
                       + ((((uint32_t)kb) ^ ((uint32_t)xrow & 7)) << 4);
            *(uint4*)(smem + X_OFF + o) = v;
        }
    }

    float acc[2][4][4];

    for (int tile = blockIdx.x; tile < numTiles; tile += gridDim.x) {
        const int base = tile * 128;
        if (tid < 128) segs[tid] = seg[base + tid];
        __syncthreads();   // (a) Xbuf STS + segs visible; prev h1 reads done

        // acc init = c[seg] gather (fp32, exact)
        #pragma unroll
        for (int mt = 0; mt < 2; ++mt) {
            const int ra = wr * 32 + mt * 16 + gr;
            const int ga = segs[ra], gb = segs[ra + 8];
            #pragma unroll
            for (int nt = 0; nt < 4; ++nt) {
                const int col = wc * 32 + nt * 8 + 2 * tg;
                float2 ca = *(const float2*)&g_c[(size_t)ga * H + col];
                float2 cb = *(const float2*)&g_c[(size_t)gb * H + col];
                acc[mt][nt][0] = ca.x; acc[mt][nt][1] = ca.y;
                acc[mt][nt][2] = cb.x; acc[mt][nt][3] = cb.y;
            }
        }

        // ---- layer1 (fp16 m16n8k16): X @ W1a ----
        #pragma unroll
        for (int ks = 0; ks < 8; ++ks) {
            uint32_t A[2][4], B[2][4];
            #pragma unroll
            for (int mt = 0; mt < 2; ++mt) {
                uint32_t ad = sb + X_OFF + (uint32_t)(arow0 + mt * 16) * 256u
                            + ((((ks << 1) + hA) ^ subA) << 4);
                ldsm4(A[mt][0], A[mt][1], A[mt][2], A[mt][3], ad);
            }
            #pragma unroll
            for (int p = 0; p < 2; ++p) {
                uint32_t bd = sb + W1_OFF + (uint32_t)(brow0 + p * 16) * 256u
                            + ((((ks << 1) + hB) ^ subB) << 4);
                ldsm4(B[p][0], B[p][1], B[p][2], B[p][3], bd);
            }
            #pragma unroll
            for (int mt = 0; mt < 2; ++mt) {
                mma16(acc[mt][0], A[mt], B[0][0], B[0][1]);
                mma16(acc[mt][1], A[mt], B[0][2], B[0][3]);
                mma16(acc[mt][2], A[mt], B[1][0], B[1][1]);
                mma16(acc[mt][3], A[mt], B[1][2], B[1][3]);
            }
        }

        // ---- epilogue1: relu, fp16 -> h1 ----
        #pragma unroll
        for (int mt = 0; mt < 2; ++mt) {
            const int ra = wr * 32 + mt * 16 + gr;
            #pragma unroll
            for (int nt = 0; nt < 4; ++nt) {
                const int col = wc * 32 + nt * 8 + 2 * tg;
                const uint32_t unit = (uint32_t)(col >> 3);
                uint32_t v01 = pack_f16x2(fmaxf(acc[mt][nt][0], 0.0f),
                                          fmaxf(acc[mt][nt][1], 0.0f));
                uint32_t o1 = (uint32_t)ra * 256u
                            + ((unit ^ ((uint32_t)ra & 7)) << 4)
                            + ((uint32_t)col & 7) * 2u;
                *(uint32_t*)(smem + H1_OFF + o1) = v01;
                uint32_t v23 = pack_f16x2(fmaxf(acc[mt][nt][2], 0.0f),
                                          fmaxf(acc[mt][nt][3], 0.0f));
                uint32_t o2 = (uint32_t)(ra + 8) * 256u
                            + ((unit ^ (((uint32_t)ra + 8) & 7)) << 4)
                            + ((uint32_t)col & 7) * 2u;
                *(uint32_t*)(smem + H1_OFF + o2) = v23;
                #pragma unroll
                for (int j = 0; j < 4; ++j) acc[mt][nt][j] = 0.0f;
            }
        }
        __syncthreads();   // (d) h1 visible; Xbuf free (layer1 done everywhere)

        // LDG next-tile X (latency hidden under layer2)
        const int nxt = tile + gridDim.x;
        float4 pa[4], pb[4];
        if (nxt < numTiles) {
            const int nb = nxt * 128;
            #pragma unroll
            for (int i = 0; i < 4; ++i) {
                const int kb = xkb0 + i;
                const float* src = &node[(size_t)(nb + xrow) * H + kb * 8];
                pa[i] = *(const float4*)src;
                pb[i] = *(const float4*)(src + 4);
            }
        }

        // ---- layer2 (fp16): h1 @ W2 ----
        #pragma unroll
        for (int ks = 0; ks < 8; ++ks) {
            uint32_t A[2][4], B[2][4];
            #pragma unroll
            for (int mt = 0; mt < 2; ++mt) {
                uint32_t ad = sb + H1_OFF + (uint32_t)(arow0 + mt * 16) * 256u
                            + ((((ks << 1) + hA) ^ subA) << 4);
                ldsm4(A[mt][0], A[mt][1], A[mt][2], A[mt][3], ad);
            }
            #pragma unroll
            for (int p = 0; p < 2; ++p) {
                uint32_t bd = sb + W2_OFF + (uint32_t)(brow0 + p * 16) * 256u
                            + ((((ks << 1) + hB) ^ subB) << 4);
                ldsm4(B[p][0], B[p][1], B[p][2], B[p][3], bd);
            }
            #pragma unroll
            for (int mt = 0; mt < 2; ++mt) {
                mma16(acc[mt][0], A[mt], B[0][0], B[0][1]);
                mma16(acc[mt][1], A[mt], B[0][2], B[0][3]);
                mma16(acc[mt][2], A[mt], B[1][0], B[1][1]);
                mma16(acc[mt][3], A[mt], B[1][2], B[1][3]);
            }
        }

        // store next-tile X into Xbuf (visible at next (a))
        if (nxt < numTiles) {
            #pragma unroll
            for (int i = 0; i < 4; ++i) {
                const int kb = xkb0 + i;
                uint4 v;
                v.x = pack_f16x2(pa[i].x, pa[i].y); v.y = pack_f16x2(pa[i].z, pa[i].w);
                v.z = pack_f16x2(pb[i].x, pb[i].y); v.w = pack_f16x2(pb[i].z, pb[i].w);
                uint32_t o = (uint32_t)xrow * 256u
                           + ((((uint32_t)kb) ^ ((uint32_t)xrow & 7)) << 4);
                *(uint4*)(smem + X_OFF + o) = v;
            }
        }

        // ---- epilogue2: +b2, relu, STG ----
        #pragma unroll
        for (int mt = 0; mt < 2; ++mt) {
            const int ra = base + wr * 32 + mt * 16 + gr;
            #pragma unroll
            for (int nt = 0; nt < 4; ++nt) {
                const int col = wc * 32 + nt * 8 + 2 * tg;
                const float bx = b2s[col], by = b2s[col + 1];
                float2 v;
                v.x = fmaxf(acc[mt][nt][0] + bx, 0.0f);
                v.y = fmaxf(acc[mt][nt][1] + by, 0.0f);
                *(float2*)&n_out[(size_t)ra * H + col] = v;
                v.x = fmaxf(acc[mt][nt][2] + bx, 0.0f);
                v.y = fmaxf(acc[mt][nt][3] + by, 0.0f);
                *(float2*)&n_out[(size_t)(ra + 8) * H + col] = v;
            }
        }
    }
}

extern "C" void kernel_launch(void* const* d_in, const int* in_sizes, int n_in,
                              void* d_out, int out_size) {
    const float* uset  = (const float*)d_in[0];   // [G, H]
    const float* unode = (const float*)d_in[1];   // [N, H]
    const int*   seg   = (const int*)d_in[2];     // [N]
    const float* Ws1   = (const float*)d_in[3];
    const float* bs1   = (const float*)d_in[4];
    const float* Ws2   = (const float*)d_in[5];
    const float* bs2   = (const float*)d_in[6];
    const float* Wn1   = (const float*)d_in[7];
    const float* bn1   = (const float*)d_in[8];
    const float* Wn2   = (const float*)d_in[9];
    const float* bn2   = (const float*)d_in[10];

    const int G = in_sizes[0] / H;
    const int N = in_sizes[1] / H;

    float* s_out = (float*)d_out;                  // [G, H]
    float* n_out = (float*)d_out + (size_t)G * H;  // [N, H]

    seg_mlp_c_kernel<<<G / 8, 128>>>(unode, seg, uset, Ws1, bs1, Ws2, bs2,
                                     Wn1, bn1, s_out, N);

    static int smem_set = 0;
    if (!smem_set) {
        cudaFuncSetAttribute(fused_node_mlp,
                             cudaFuncAttributeMaxDynamicSharedMemorySize, F_SMEM);
        smem_set = 1;
    }
    const int numTiles = N / 128;
    const int grid = numTiles < 148 ? numTiles : 148;
    fused_node_mlp<<<grid, 512, F_SMEM>>>(unode, seg, Wn1, Wn2, bn2, n_out, numTiles);
}